// round 2
// baseline (speedup 1.0000x reference)
#include <cuda_runtime.h>
#include <math.h>
#include <float.h>

#define BB 4
#define CC 256
#define HHH 128
#define WWW 128
#define HW (HHH*WWW)
#define CHW (CC*HW)
#define TOT (BB*CHW)

// ---------------- scratch (device globals; no allocation allowed) ----------------
__device__ float g_bufA[TOT];
__device__ float g_bufB[TOT];
__device__ float g_rmax[BB*CC*HHH];
__device__ float g_cmax[BB*CC*WWW];
__device__ float g_wt_up[CC*9*CC];
__device__ float g_wt_down[CC*9*CC];
__device__ float g_wt_p[CC*9*CC];
__device__ float g_wt_c2[CC*9*CC];
__device__ float g_wt_c1[CC*CC];

// ---------------- weight transpose: OIHW -> [(ic*R + r)*256 + oc] ----------------
__global__ void transpose_w_kernel(const float* __restrict__ src,
                                   float* __restrict__ dst, int R) {
    int i = blockIdx.x * 256 + threadIdx.x;
    int total = CC * CC * R;
    if (i >= total) return;
    int r  = i % R;
    int ic = (i / R) % CC;
    int oc = i / (R * CC);
    dst[(ic * R + r) * CC + oc] = src[i];
}

// ---------------- 3x3 conv + BN (+optional ReLU) ----------------
// CTA: 256 threads, tile = 128 px (8h x 16w) x 128 oc. Thread = 8 px x 8 oc.
template<bool RELU>
__global__ __launch_bounds__(256, 2) void conv3_kernel(
    const float* __restrict__ in, const float* __restrict__ wt,
    const float* __restrict__ gg, const float* __restrict__ bbp,
    const float* __restrict__ mm, const float* __restrict__ vv,
    float* __restrict__ out)
{
    __shared__ float s_in[8][10][18];     // [ic][row][col]
    __shared__ float s_w[8 * 9 * 128];    // [(ic*9 + r)*128 + oc_local]

    const int wt0 = blockIdx.x * 16;
    const int ht0 = blockIdx.y * 8;
    const int b   = blockIdx.z >> 1;
    const int ocb = (blockIdx.z & 1) * 128;
    const int tid = threadIdx.x;
    const int tx  = tid & 15;     // oc group: oc_local = tx*8..tx*8+7
    const int ty  = tid >> 4;     // px group
    const int h_loc = ty >> 1;          // 0..7
    const int wb    = (ty & 1) * 8;     // 0 or 8

    float acc[8][8];
#pragma unroll
    for (int j = 0; j < 8; ++j)
#pragma unroll
        for (int o = 0; o < 8; ++o) acc[j][o] = 0.f;

    const float* inb = in + (size_t)b * CHW;

    for (int ic0 = 0; ic0 < CC; ic0 += 8) {
        __syncthreads();
        // input tile (with halo, zero padded): 8 ic x 10 rows x 18 cols
        for (int l = tid; l < 8 * 10 * 18; l += 256) {
            int col  = l % 18;
            int rest = l / 18;
            int row  = rest % 10;
            int ic   = rest / 10;
            int gh = ht0 + row - 1;
            int gw = wt0 + col - 1;
            float val = 0.f;
            if ((unsigned)gh < HHH && (unsigned)gw < WWW)
                val = inb[(size_t)(ic0 + ic) * HW + gh * WWW + gw];
            s_in[ic][row][col] = val;
        }
        // weights: coalesced rows of 128 floats from transposed layout
        for (int l = tid; l < 8 * 9 * 128; l += 256) {
            int ocl = l & 127;
            int kr  = l >> 7;   // ic_local*9 + r
            s_w[l] = wt[(size_t)(ic0 * 9 + kr) * CC + ocb + ocl];
        }
        __syncthreads();

#pragma unroll 1
        for (int ic = 0; ic < 8; ++ic) {
#pragma unroll
            for (int ky = 0; ky < 3; ++ky) {
                float xin[10];
#pragma unroll
                for (int j = 0; j < 10; ++j) xin[j] = s_in[ic][h_loc + ky][wb + j];
#pragma unroll
                for (int kx = 0; kx < 3; ++kx) {
                    const float4* wp = (const float4*)&s_w[(ic * 9 + ky * 3 + kx) * 128 + tx * 8];
                    float4 w0 = wp[0];
                    float4 w1 = wp[1];
                    float wr[8] = {w0.x, w0.y, w0.z, w0.w, w1.x, w1.y, w1.z, w1.w};
#pragma unroll
                    for (int j = 0; j < 8; ++j) {
                        float xv = xin[j + kx];
#pragma unroll
                        for (int o = 0; o < 8; ++o)
                            acc[j][o] = fmaf(xv, wr[o], acc[j][o]);
                    }
                }
            }
        }
    }

    // epilogue: BN (+ReLU), write 8px x 8oc
#pragma unroll
    for (int o = 0; o < 8; ++o) {
        int oc = ocb + tx * 8 + o;
        float s  = gg[oc] * rsqrtf(vv[oc] + 1e-5f);
        float sh = bbp[oc] - mm[oc] * s;
        float* op = out + ((size_t)b * CC + oc) * HW + (ht0 + h_loc) * WWW + wt0 + wb;
#pragma unroll
        for (int j = 0; j < 8; ++j) {
            float v = acc[j][o] * s + sh;
            if (RELU) v = fmaxf(v, 0.f);
            op[j] = v;
        }
    }
}

// ---------------- row max over W (one warp per row) ----------------
__global__ void rowmax_kernel(const float* __restrict__ in, float* __restrict__ out) {
    int row  = blockIdx.x * 8 + (threadIdx.x >> 5);
    int lane = threadIdx.x & 31;
    const float* p = in + (size_t)row * WWW;
    float m = fmaxf(fmaxf(p[lane], p[lane + 32]), fmaxf(p[lane + 64], p[lane + 96]));
#pragma unroll
    for (int s = 16; s > 0; s >>= 1)
        m = fmaxf(m, __shfl_xor_sync(0xFFFFFFFFu, m, s));
    if (lane == 0) out[row] = m;
}

// ---------------- column max over H ----------------
__global__ void colmax_kernel(const float* __restrict__ in, float* __restrict__ out) {
    int idx = blockIdx.x * 256 + threadIdx.x;   // (b*C + c)*W + w
    int w  = idx & 127;
    int bc = idx >> 7;
    const float* p = in + (size_t)bc * HW + w;
    float m = -FLT_MAX;
#pragma unroll 4
    for (int h = 0; h < HHH; ++h) m = fmaxf(m, p[h * WWW]);
    out[idx] = m;
}

// ---------------- S = Rmax (bcast over w) + Cmax (bcast over h) ----------------
__global__ void builds_kernel(const float* __restrict__ rmax,
                              const float* __restrict__ cmax,
                              float* __restrict__ out) {
    int i = blockIdx.x * 256 + threadIdx.x;
    int w   = i & 127;
    int bch = i >> 7;          // bc*128 + h
    int bc  = i >> 14;
    out[i] = rmax[bch] + cmax[bc * 128 + w];
}

// ---------------- fused: relu( merge + BN(conv1x1(x)) ) ----------------
__global__ __launch_bounds__(256, 2) void fused1x1_kernel(
    const float* __restrict__ x, const float* __restrict__ wt1,
    const float* __restrict__ gg, const float* __restrict__ bbp,
    const float* __restrict__ mm, const float* __restrict__ vv,
    const float* __restrict__ merge, float* __restrict__ out)
{
    __shared__ float s_x[16 * 128];
    __shared__ float s_w[16 * 128];
    const int ocb = blockIdx.x * 128;
    const int h   = blockIdx.y;
    const int b   = blockIdx.z;
    const int tid = threadIdx.x;
    const int tx = tid & 15;
    const int ty = tid >> 4;

    float acc[8][8];
#pragma unroll
    for (int j = 0; j < 8; ++j)
#pragma unroll
        for (int o = 0; o < 8; ++o) acc[j][o] = 0.f;

    for (int ic0 = 0; ic0 < CC; ic0 += 16) {
        __syncthreads();
        for (int l = tid; l < 2048; l += 256) {
            int col = l & 127;
            int ic  = l >> 7;
            s_x[l] = x[((size_t)(b * CC + ic0 + ic)) * HW + h * WWW + col];
            s_w[l] = wt1[(ic0 + ic) * CC + ocb + col];
        }
        __syncthreads();
#pragma unroll 1
        for (int ic = 0; ic < 16; ++ic) {
            float xr[8];
#pragma unroll
            for (int j = 0; j < 8; ++j) xr[j] = s_x[ic * 128 + ty * 8 + j];
            const float4* wp = (const float4*)&s_w[ic * 128 + tx * 8];
            float4 w0 = wp[0];
            float4 w1 = wp[1];
            float wr[8] = {w0.x, w0.y, w0.z, w0.w, w1.x, w1.y, w1.z, w1.w};
#pragma unroll
            for (int j = 0; j < 8; ++j)
#pragma unroll
                for (int o = 0; o < 8; ++o)
                    acc[j][o] = fmaf(xr[j], wr[o], acc[j][o]);
        }
    }

#pragma unroll
    for (int o = 0; o < 8; ++o) {
        int oc = ocb + tx * 8 + o;
        float s  = gg[oc] * rsqrtf(vv[oc] + 1e-5f);
        float sh = bbp[oc] - mm[oc] * s;
        size_t base = ((size_t)b * CC + oc) * HW + h * WWW + ty * 8;
#pragma unroll
        for (int j = 0; j < 8; ++j) {
            float v = acc[j][o] * s + sh + merge[base + j];
            out[base + j] = fmaxf(v, 0.f);
        }
    }
}

// ---------------- launch ----------------
extern "C" void kernel_launch(void* const* d_in, const int* in_sizes, int n_in,
                              void* d_out, int out_size) {
    (void)in_sizes; (void)n_in; (void)out_size;
    const float* x      = (const float*)d_in[0];
    const float* w_up   = (const float*)d_in[1];
    const float* g_up   = (const float*)d_in[2];
    const float* b_up   = (const float*)d_in[3];
    const float* m_up   = (const float*)d_in[4];
    const float* v_up   = (const float*)d_in[5];
    const float* w_down = (const float*)d_in[6];
    const float* g_down = (const float*)d_in[7];
    const float* b_down = (const float*)d_in[8];
    const float* m_down = (const float*)d_in[9];
    const float* v_down = (const float*)d_in[10];
    const float* w_p    = (const float*)d_in[11];
    const float* g_p    = (const float*)d_in[12];
    const float* b_p    = (const float*)d_in[13];
    const float* m_p    = (const float*)d_in[14];
    const float* v_p    = (const float*)d_in[15];
    const float* w_c1   = (const float*)d_in[16];
    const float* g_c1   = (const float*)d_in[17];
    const float* b_c1   = (const float*)d_in[18];
    const float* m_c1   = (const float*)d_in[19];
    const float* v_c1   = (const float*)d_in[20];
    const float* w_c2   = (const float*)d_in[21];
    const float* g_c2   = (const float*)d_in[22];
    const float* b_c2   = (const float*)d_in[23];
    const float* m_c2   = (const float*)d_in[24];
    const float* v_c2   = (const float*)d_in[25];
    float* out = (float*)d_out;

    float *A, *B, *rmax, *cmax, *wtu, *wtd, *wtp, *wtc2, *wtc1;
    cudaGetSymbolAddress((void**)&A,    g_bufA);
    cudaGetSymbolAddress((void**)&B,    g_bufB);
    cudaGetSymbolAddress((void**)&rmax, g_rmax);
    cudaGetSymbolAddress((void**)&cmax, g_cmax);
    cudaGetSymbolAddress((void**)&wtu,  g_wt_up);
    cudaGetSymbolAddress((void**)&wtd,  g_wt_down);
    cudaGetSymbolAddress((void**)&wtp,  g_wt_p);
    cudaGetSymbolAddress((void**)&wtc2, g_wt_c2);
    cudaGetSymbolAddress((void**)&wtc1, g_wt_c1);

    const int TB = 256;
    int nt9 = CC * CC * 9;
    transpose_w_kernel<<<(nt9 + TB - 1) / TB, TB>>>(w_up,   wtu,  9);
    transpose_w_kernel<<<(nt9 + TB - 1) / TB, TB>>>(w_down, wtd,  9);
    transpose_w_kernel<<<(nt9 + TB - 1) / TB, TB>>>(w_p,    wtp,  9);
    transpose_w_kernel<<<(nt9 + TB - 1) / TB, TB>>>(w_c2,   wtc2, 9);
    transpose_w_kernel<<<(CC * CC + TB - 1) / TB, TB>>>(w_c1, wtc1, 1);

    dim3 cgrid(8, 16, 8);   // w-tiles, h-tiles, b*2 + oc_block

    // up / down conv-bn-relu
    conv3_kernel<true><<<cgrid, TB>>>(x, wtu, g_up, b_up, m_up, v_up, A);
    conv3_kernel<true><<<cgrid, TB>>>(x, wtd, g_down, b_down, m_down, v_down, B);

    // corner pools collapse to global row/col max
    rowmax_kernel<<<(BB * CC * HHH) / 8, TB>>>(A, rmax);
    colmax_kernel<<<(BB * CC * WWW) / TB, TB>>>(B, cmax);
    builds_kernel<<<TOT / TB, TB>>>(rmax, cmax, A);

    // merge = BN(conv3x3(S))
    conv3_kernel<false><<<cgrid, TB>>>(A, wtp, g_p, b_p, m_p, v_p, B);

    // relu1 = relu(merge + BN(conv1x1(x)))
    fused1x1_kernel<<<dim3(2, 128, 4), TB>>>(x, wtc1, g_c1, b_c1, m_c1, v_c1, B, A);

    // out = CBR(relu1, w_c2)
    conv3_kernel<true><<<cgrid, TB>>>(A, wtc2, g_c2, b_c2, m_c2, v_c2, out);
}